// round 11
// baseline (speedup 1.0000x reference)
#include <cuda_runtime.h>
#include <cstdint>

#define N_NODES 16384
#define HDIM    64
#define MAXN    160          // max nnz/row: Binomial(16384,0.004)+1, mean 66, ~11 sigma headroom
#define NBLK    256          // gemm blocks (64 rows each)
#define BN_EPS  1e-5f

// ---------------- device scratch (no allocations allowed) ----------------
__device__ int   g_idx[N_NODES * MAXN];     // CSR-ish column indices per row
__device__ int   g_nnz[N_NODES];            // row degree (= row sum of adj)
__device__ __align__(16) float g_pooled[N_NODES * HDIM];
__device__ __align__(16) float g_t[N_NODES * HDIM];
__device__ __align__(16) float g_t2[N_NODES * HDIM];
__device__ __align__(16) float g_part[NBLK * 128];   // per-block [sum(64) | sumsq(64)]
__device__ __align__(16) float g_ab[128];            // BN affine: a[64], b[64]

// ---------------- device helper: block-redundant BN finalize into smem ----------------
// 256 threads reduce g_part (NBLK x 128) -> ab[0..63]=a, ab[64..127]=b.
// Caller must __syncthreads() after (done inside).
__device__ __forceinline__ void bn_reduce_smem(const float* __restrict__ gv,
                                               const float* __restrict__ bev,
                                               float* ab /*[128] smem*/,
                                               float (*sred)[128] /*[4][128] smem*/,
                                               int tid) {
    int col = tid & 63;
    int q   = tid >> 6;                 // quarter 0..3
    float s = 0.f, qq = 0.f;
    for (int b = q; b < NBLK; b += 4) {
        s  += g_part[(size_t)b * 128 + col];
        qq += g_part[(size_t)b * 128 + 64 + col];
    }
    sred[q][col]      = s;
    sred[q][64 + col] = qq;
    __syncthreads();
    if (tid < 64) {
        float S = (sred[0][tid] + sred[1][tid]) + (sred[2][tid] + sred[3][tid]);
        float Q = (sred[0][64 + tid] + sred[1][64 + tid]) +
                  (sred[2][64 + tid] + sred[3][64 + tid]);
        const float invn = 1.0f / (float)N_NODES;
        float mean = S * invn;
        float var  = Q * invn - mean * mean;
        float a = gv[tid] * rsqrtf(var + BN_EPS);
        ab[tid]      = a;
        ab[64 + tid] = bev[tid] - mean * a;
    }
    __syncthreads();
}

// ---------------- K1: fused adj scan + layer-0 mean aggregation ----------------
// One warp per row; 8 coalesced LDG.128 per thread per iter (512B warp loads);
// measured at 80% of HBM spec (R10) — at the bandwidth floor.
__global__ __launch_bounds__(256) void scan_agg(const float* __restrict__ adj,
                                                const float* __restrict__ x,
                                                float* __restrict__ pooled) {
    int lane   = threadIdx.x & 31;
    int wlocal = threadIdx.x >> 5;
    int row    = (blockIdx.x << 3) + wlocal;        // 2048 blocks * 8 warps

    __shared__ int snnz[8];
    __shared__ int ids[8][MAXN];
    if (lane == 0) snnz[wlocal] = 0;
    __syncwarp();

    const uint4* base = reinterpret_cast<const uint4*>(adj + (size_t)row * N_NODES);
    int* rowidx = g_idx + (size_t)row * MAXN;

    for (int t = 0; t < 16; t++) {
        int ibase = t * 256;
        uint4 u[8];
        #pragma unroll
        for (int k = 0; k < 8; k++)
            u[k] = __ldcs(base + ibase + k * 32 + lane);

        unsigned any = 0;
        #pragma unroll
        for (int k = 0; k < 8; k++)
            any |= (u[k].x | u[k].y | u[k].z | u[k].w);

        if (any) {
            int loc[32];
            int cnt = 0;
            #pragma unroll
            for (int k = 0; k < 8; k++) {
                unsigned mk = u[k].x | u[k].y | u[k].z | u[k].w;
                if (mk) {
                    int col0 = (ibase + k * 32 + lane) * 4;
                    if (u[k].x) loc[cnt++] = col0;
                    if (u[k].y) loc[cnt++] = col0 + 1;
                    if (u[k].z) loc[cnt++] = col0 + 2;
                    if (u[k].w) loc[cnt++] = col0 + 3;
                }
            }
            int pos = atomicAdd(&snnz[wlocal], cnt);
            if (pos + cnt <= MAXN) {
                for (int i = 0; i < cnt; i++) {
                    ids[wlocal][pos + i] = loc[i];
                    rowidx[pos + i]      = loc[i];
                }
            }
        }
    }
    __syncwarp();
    int nnz = snnz[wlocal];
    if (lane == 0) g_nnz[row] = nnz;

    // phase 2: gather x over id list -> pooled[row,:]
    int half = lane >> 4;
    int cg   = lane & 15;
    float4 acc = make_float4(0.f, 0.f, 0.f, 0.f);

    int k = half;
    for (; k + 2 < nnz; k += 4) {
        int i0 = ids[wlocal][k];
        int i1 = ids[wlocal][k + 2];
        float4 v0 = *reinterpret_cast<const float4*>(x + (size_t)i0 * HDIM + cg * 4);
        float4 v1 = *reinterpret_cast<const float4*>(x + (size_t)i1 * HDIM + cg * 4);
        acc.x += v0.x + v1.x; acc.y += v0.y + v1.y;
        acc.z += v0.z + v1.z; acc.w += v0.w + v1.w;
    }
    if (k < nnz) {
        int i0 = ids[wlocal][k];
        float4 v0 = *reinterpret_cast<const float4*>(x + (size_t)i0 * HDIM + cg * 4);
        acc.x += v0.x; acc.y += v0.y; acc.z += v0.z; acc.w += v0.w;
    }
    acc.x += __shfl_down_sync(0xffffffffu, acc.x, 16);
    acc.y += __shfl_down_sync(0xffffffffu, acc.y, 16);
    acc.z += __shfl_down_sync(0xffffffffu, acc.z, 16);
    acc.w += __shfl_down_sync(0xffffffffu, acc.w, 16);
    if (half == 0) {
        float inv = 1.0f / (float)nnz;
        float4 r = make_float4(acc.x * inv, acc.y * inv, acc.z * inv, acc.w * inv);
        *reinterpret_cast<float4*>(pooled + (size_t)row * HDIM + cg * 4) = r;
    }
}

// ---------------- K2: sparse mean aggregation, float4 gather, MLP=4 ----------------
// APPLY=1 fuses relu(a*x+b) (g_ab, from bn_finalize) into the gather.
template <int APPLY>
__global__ __launch_bounds__(256) void agg(const float* __restrict__ src,
                                           float* __restrict__ out) {
    int rl  = threadIdx.x >> 6;
    int t6  = threadIdx.x & 63;
    int grp = t6 >> 4;
    int cg  = t6 & 15;
    int r   = ((int)blockIdx.x << 2) + rl;

    __shared__ int    ids[4][MAXN];
    __shared__ float4 red[4][4][16];

    int nnz = g_nnz[r];
    for (int i = t6; i < nnz; i += 64) ids[rl][i] = g_idx[(size_t)r * MAXN + i];
    __syncthreads();

    float4 bna, bnb;
    if (APPLY) {
        bna = *reinterpret_cast<const float4*>(&g_ab[cg * 4]);
        bnb = *reinterpret_cast<const float4*>(&g_ab[64 + cg * 4]);
    }

    float4 acc = make_float4(0.f, 0.f, 0.f, 0.f);
    int k = grp;
    for (; k + 12 < nnz; k += 16) {
        int i0 = ids[rl][k];
        int i1 = ids[rl][k + 4];
        int i2 = ids[rl][k + 8];
        int i3 = ids[rl][k + 12];
        float4 v0 = *reinterpret_cast<const float4*>(src + (size_t)i0 * HDIM + cg * 4);
        float4 v1 = *reinterpret_cast<const float4*>(src + (size_t)i1 * HDIM + cg * 4);
        float4 v2 = *reinterpret_cast<const float4*>(src + (size_t)i2 * HDIM + cg * 4);
        float4 v3 = *reinterpret_cast<const float4*>(src + (size_t)i3 * HDIM + cg * 4);
        if (APPLY) {
            v0.x = fmaxf(fmaf(bna.x, v0.x, bnb.x), 0.f);
            v0.y = fmaxf(fmaf(bna.y, v0.y, bnb.y), 0.f);
            v0.z = fmaxf(fmaf(bna.z, v0.z, bnb.z), 0.f);
            v0.w = fmaxf(fmaf(bna.w, v0.w, bnb.w), 0.f);
            v1.x = fmaxf(fmaf(bna.x, v1.x, bnb.x), 0.f);
            v1.y = fmaxf(fmaf(bna.y, v1.y, bnb.y), 0.f);
            v1.z = fmaxf(fmaf(bna.z, v1.z, bnb.z), 0.f);
            v1.w = fmaxf(fmaf(bna.w, v1.w, bnb.w), 0.f);
            v2.x = fmaxf(fmaf(bna.x, v2.x, bnb.x), 0.f);
            v2.y = fmaxf(fmaf(bna.y, v2.y, bnb.y), 0.f);
            v2.z = fmaxf(fmaf(bna.z, v2.z, bnb.z), 0.f);
            v2.w = fmaxf(fmaf(bna.w, v2.w, bnb.w), 0.f);
            v3.x = fmaxf(fmaf(bna.x, v3.x, bnb.x), 0.f);
            v3.y = fmaxf(fmaf(bna.y, v3.y, bnb.y), 0.f);
            v3.z = fmaxf(fmaf(bna.z, v3.z, bnb.z), 0.f);
            v3.w = fmaxf(fmaf(bna.w, v3.w, bnb.w), 0.f);
        }
        acc.x += (v0.x + v1.x) + (v2.x + v3.x);
        acc.y += (v0.y + v1.y) + (v2.y + v3.y);
        acc.z += (v0.z + v1.z) + (v2.z + v3.z);
        acc.w += (v0.w + v1.w) + (v2.w + v3.w);
    }
    for (; k < nnz; k += 4) {
        int i0 = ids[rl][k];
        float4 v0 = *reinterpret_cast<const float4*>(src + (size_t)i0 * HDIM + cg * 4);
        if (APPLY) {
            v0.x = fmaxf(fmaf(bna.x, v0.x, bnb.x), 0.f);
            v0.y = fmaxf(fmaf(bna.y, v0.y, bnb.y), 0.f);
            v0.z = fmaxf(fmaf(bna.z, v0.z, bnb.z), 0.f);
            v0.w = fmaxf(fmaf(bna.w, v0.w, bnb.w), 0.f);
        }
        acc.x += v0.x; acc.y += v0.y; acc.z += v0.z; acc.w += v0.w;
    }

    red[rl][grp][cg] = acc;
    __syncthreads();

    int col = t6;
    const float* r0 = reinterpret_cast<const float*>(&red[rl][0][col >> 2]);
    const float* r1 = reinterpret_cast<const float*>(&red[rl][1][col >> 2]);
    const float* r2 = reinterpret_cast<const float*>(&red[rl][2][col >> 2]);
    const float* r3 = reinterpret_cast<const float*>(&red[rl][3][col >> 2]);
    int comp = col & 3;
    float s = (r0[comp] + r1[comp]) + (r2[comp] + r3[comp]);
    out[(size_t)r * HDIM + col] = s / (float)g_nnz[r];
}

// ---------------- K3: register-blocked GEMM [16384,64]@[64,64] + bias + BN stats
// 64-row tiles, 4x4 register block per thread (R8 version).
// MODE==1: block first reduces g_part -> BN affine in smem, then applies
// relu(a*x+b) to the input tile (fuses bn_finalize into the gemm).
template <int MODE>
__global__ __launch_bounds__(256) void gemm64(const float* __restrict__ in,
                                              const float* __restrict__ W,
                                              const float* __restrict__ bias,
                                              const float* __restrict__ gv,
                                              const float* __restrict__ bev,
                                              float* __restrict__ out,
                                              float* __restrict__ part) {
    __shared__ __align__(16) float Ws[64 * 64];      // 16KB
    __shared__ __align__(16) float Is[64][72];       // 18KB
    __shared__ float redm[16][64];                   // 4KB
    __shared__ float ab[128];
    __shared__ float sred[4][128];                   // 2KB

    int tid = threadIdx.x;

    if (MODE == 1)
        bn_reduce_smem(gv, bev, ab, sred, tid);      // includes trailing syncthreads

    const float4* W4 = reinterpret_cast<const float4*>(W);
    float4* Ws4 = reinterpret_cast<float4*>(Ws);
    #pragma unroll
    for (int i = tid; i < 1024; i += 256) Ws4[i] = W4[i];

    int row0 = (int)blockIdx.x * 64;
    const float4* in4 = reinterpret_cast<const float4*>(in + (size_t)row0 * HDIM);
    #pragma unroll
    for (int i = tid; i < 1024; i += 256) {
        int rr = i >> 4, cg = i & 15;
        float4 v = in4[i];
        if (MODE == 1) {
            float4 a4 = *reinterpret_cast<const float4*>(&ab[cg * 4]);
            float4 b4 = *reinterpret_cast<const float4*>(&ab[64 + cg * 4]);
            v.x = fmaxf(fmaf(a4.x, v.x, b4.x), 0.f);
            v.y = fmaxf(fmaf(a4.y, v.y, b4.y), 0.f);
            v.z = fmaxf(fmaf(a4.z, v.z, b4.z), 0.f);
            v.w = fmaxf(fmaf(a4.w, v.w, b4.w), 0.f);
        }
        *reinterpret_cast<float4*>(&Is[rr][cg * 4]) = v;
    }
    __syncthreads();

    int ty = tid >> 4;
    int tx = tid & 15;

    float acc[4][4];
    float4 bv = *reinterpret_cast<const float4*>(bias + tx * 4);
    #pragma unroll
    for (int r = 0; r < 4; r++) {
        acc[r][0] = bv.x; acc[r][1] = bv.y; acc[r][2] = bv.z; acc[r][3] = bv.w;
    }

    #pragma unroll
    for (int k = 0; k < 64; k += 4) {
        float4 w0 = *reinterpret_cast<const float4*>(&Ws[(k + 0) * 64 + tx * 4]);
        float4 w1 = *reinterpret_cast<const float4*>(&Ws[(k + 1) * 64 + tx * 4]);
        float4 w2 = *reinterpret_cast<const float4*>(&Ws[(k + 2) * 64 + tx * 4]);
        float4 w3 = *reinterpret_cast<const float4*>(&Ws[(k + 3) * 64 + tx * 4]);
        #pragma unroll
        for (int r = 0; r < 4; r++) {
            float4 iv = *reinterpret_cast<const float4*>(&Is[ty * 4 + r][k]);
            acc[r][0] = fmaf(iv.x, w0.x, acc[r][0]);
            acc[r][1] = fmaf(iv.x, w0.y, acc[r][1]);
            acc[r][2] = fmaf(iv.x, w0.z, acc[r][2]);
            acc[r][3] = fmaf(iv.x, w0.w, acc[r][3]);
            acc[r][0] = fmaf(iv.y, w1.x, acc[r][0]);
            acc[r][1] = fmaf(iv.y, w1.y, acc[r][1]);
            acc[r][2] = fmaf(iv.y, w1.z, acc[r][2]);
            acc[r][3] = fmaf(iv.y, w1.w, acc[r][3]);
            acc[r][0] = fmaf(iv.z, w2.x, acc[r][0]);
            acc[r][1] = fmaf(iv.z, w2.y, acc[r][1]);
            acc[r][2] = fmaf(iv.z, w2.z, acc[r][2]);
            acc[r][3] = fmaf(iv.z, w2.w, acc[r][3]);
            acc[r][0] = fmaf(iv.w, w3.x, acc[r][0]);
            acc[r][1] = fmaf(iv.w, w3.y, acc[r][1]);
            acc[r][2] = fmaf(iv.w, w3.z, acc[r][2]);
            acc[r][3] = fmaf(iv.w, w3.w, acc[r][3]);
        }
    }

    #pragma unroll
    for (int r = 0; r < 4; r++) {
        float4 o = make_float4(acc[r][0], acc[r][1], acc[r][2], acc[r][3]);
        *reinterpret_cast<float4*>(out + (size_t)(row0 + ty * 4 + r) * HDIM + tx * 4) = o;
    }

    // per-block column stats: sum then sumsq
    float s[4];
    #pragma unroll
    for (int j = 0; j < 4; j++)
        s[j] = (acc[0][j] + acc[1][j]) + (acc[2][j] + acc[3][j]);
    #pragma unroll
    for (int j = 0; j < 4; j++) redm[ty][tx * 4 + j] = s[j];
    __syncthreads();
    if (tid < 64) {
        float v = 0.f;
        #pragma unroll
        for (int i = 0; i < 16; i++) v += redm[i][tid];
        part[(size_t)blockIdx.x * 128 + tid] = v;
    }
    __syncthreads();
    #pragma unroll
    for (int j = 0; j < 4; j++) {
        float q = (acc[0][j] * acc[0][j] + acc[1][j] * acc[1][j]) +
                  (acc[2][j] * acc[2][j] + acc[3][j] * acc[3][j]);
        redm[ty][tx * 4 + j] = q;
    }
    __syncthreads();
    if (tid < 64) {
        float v = 0.f;
        #pragma unroll
        for (int i = 0; i < 16; i++) v += redm[i][tid];
        part[(size_t)blockIdx.x * 128 + 64 + tid] = v;
    }
}

// ---------------- K4: reduce partials -> g_ab (kept only before agg<1>) ----------------
__global__ __launch_bounds__(256) void bn_finalize(const float* __restrict__ g,
                                                   const float* __restrict__ be) {
    int c = blockIdx.x;
    int t = threadIdx.x;

    float s = 0.f, q = 0.f;
    #pragma unroll
    for (int b = t; b < NBLK; b += 256) {
        s += g_part[(size_t)b * 128 + c];
        q += g_part[(size_t)b * 128 + 64 + c];
    }
    __shared__ float ss[256];
    __shared__ float qq[256];
    ss[t] = s; qq[t] = q;
    __syncthreads();
    #pragma unroll
    for (int o = 128; o > 0; o >>= 1) {
        if (t < o) { ss[t] += ss[t + o]; qq[t] += qq[t + o]; }
        __syncthreads();
    }
    if (t == 0) {
        const float invn = 1.0f / (float)N_NODES;
        float mean = ss[0] * invn;
        float var  = qq[0] * invn - mean * mean;
        float a = g[c] * rsqrtf(var + BN_EPS);
        g_ab[c]      = a;
        g_ab[64 + c] = be[c] - mean * a;
    }
}

// ---------------- K5: fused final BN+ReLU + h_nodes write + graph readout ----------------
// Block g: reduces g_part -> affine (redundant, cheap), then streams its gp row;
// wherever gp weight != 0 (each node belongs to exactly one graph) computes
// h = relu(a*t2+b), writes h_nodes, accumulates w*h -> pooled_h[g,:].
__global__ __launch_bounds__(256) void pool_fused(const float* __restrict__ gp,
                                                  const float* __restrict__ t2,
                                                  const float* __restrict__ gv,
                                                  const float* __restrict__ bev,
                                                  float* __restrict__ h_nodes,
                                                  float* __restrict__ out) {
    __shared__ float ab[128];
    __shared__ float sred[4][128];
    __shared__ float red[4][64];

    int tid = threadIdx.x;
    bn_reduce_smem(gv, bev, ab, sred, tid);

    int g    = blockIdx.x;              // 128 graphs
    int c    = tid & 63;
    int lane = tid >> 6;                // 4 node-lanes
    const float* gprow = gp + (size_t)g * N_NODES;
    float a_c = ab[c];
    float b_c = ab[64 + c];

    float acc = 0.f;
    for (int n0 = lane; n0 < N_NODES; n0 += 32) {
        #pragma unroll
        for (int u = 0; u < 8; u++) {
            int n = n0 + u * 4;
            float w = __ldcs(gprow + n);
            if (w != 0.f) {
                float h = fmaxf(fmaf(a_c, t2[(size_t)n * HDIM + c], b_c), 0.f);
                h_nodes[(size_t)n * HDIM + c] = h;
                acc = fmaf(w, h, acc);
            }
        }
    }
    red[lane][c] = acc;
    __syncthreads();
    if (tid < 64)
        out[(size_t)g * HDIM + tid] =
            (red[0][tid] + red[1][tid]) + (red[2][tid] + red[3][tid]);
}

// ---------------- launch ----------------
extern "C" void kernel_launch(void* const* d_in, const int* in_sizes, int n_in,
                              void* d_out, int out_size) {
    const float* x   = (const float*)d_in[0];
    const float* adj = (const float*)d_in[1];
    const float* gp  = (const float*)d_in[2];

    const float* P[16];
    for (int i = 0; i < 16; i++) P[i] = (const float*)d_in[3 + i];

    float* out      = (float*)d_out;
    float* h_nodes  = out + 128 * HDIM;   // [16384,64] after the [128,64] readout

    float *pooled, *t, *t2, *part;
    cudaGetSymbolAddress((void**)&pooled, g_pooled);
    cudaGetSymbolAddress((void**)&t,      g_t);
    cudaGetSymbolAddress((void**)&t2,     g_t2);
    cudaGetSymbolAddress((void**)&part,   g_part);

    // 1) fused: adj scan -> CSR + degrees + layer-0 aggregation (single launch)
    scan_agg<<<2048, 256>>>(adj, x, pooled);

    // ---- layer 0 MLP (inner bn fused into gemm<1>) ----
    gemm64<0><<<NBLK, 256>>>(pooled, P[0], P[1], nullptr, nullptr, t, part);
    gemm64<1><<<NBLK, 256>>>(t, P[4], P[5], P[2], P[3], t2, part);
    bn_finalize<<<64, 256>>>(P[6], P[7]);               // outer BN (g_0, be_0) for agg

    // ---- layer 1 (outer BN+ReLU of layer 0 fused into the gather) ----
    agg<1><<<N_NODES / 4, 256>>>(t2, pooled);
    gemm64<0><<<NBLK, 256>>>(pooled, P[8], P[9], nullptr, nullptr, t, part);
    gemm64<1><<<NBLK, 256>>>(t, P[12], P[13], P[10], P[11], t2, part);

    // ---- final outer BN + ReLU + h_nodes + graph readout (one kernel) ----
    pool_fused<<<128, 256>>>(gp, t2, P[14], P[15], h_nodes, out);

    (void)in_sizes; (void)n_in; (void)out_size;
}

// round 12
// speedup vs baseline: 1.7288x; 1.7288x over previous
#include <cuda_runtime.h>
#include <cstdint>

#define N_NODES 16384
#define HDIM    64
#define MAXN    160          // max nnz/row: Binomial(16384,0.004)+1, mean 66, ~11 sigma headroom
#define NBLK    256          // gemm blocks (64 rows each)
#define BN_EPS  1e-5f

// ---------------- device scratch (no allocations allowed) ----------------
__device__ int   g_idx[N_NODES * MAXN];     // CSR-ish column indices per row
__device__ int   g_nnz[N_NODES];            // row degree (= row sum of adj)
__device__ __align__(16) float g_pooled[N_NODES * HDIM];
__device__ __align__(16) float g_t[N_NODES * HDIM];
__device__ __align__(16) float g_t2[N_NODES * HDIM];
__device__ __align__(16) float g_part[NBLK * 128];   // per-block [sum(64) | sumsq(64)]
__device__ __align__(16) float g_ab[128];            // BN affine: a[64], b[64]

// ---------------- K1: fused adj scan + layer-0 mean aggregation ----------------
// One warp per row; 8 coalesced LDG.128 per thread per iter (512B warp loads);
// measured at 80% of HBM spec (R10) — at the bandwidth floor.
__global__ __launch_bounds__(256) void scan_agg(const float* __restrict__ adj,
                                                const float* __restrict__ x,
                                                float* __restrict__ pooled) {
    int lane   = threadIdx.x & 31;
    int wlocal = threadIdx.x >> 5;
    int row    = (blockIdx.x << 3) + wlocal;        // 2048 blocks * 8 warps

    __shared__ int snnz[8];
    __shared__ int ids[8][MAXN];
    if (lane == 0) snnz[wlocal] = 0;
    __syncwarp();

    const uint4* base = reinterpret_cast<const uint4*>(adj + (size_t)row * N_NODES);
    int* rowidx = g_idx + (size_t)row * MAXN;

    for (int t = 0; t < 16; t++) {
        int ibase = t * 256;
        uint4 u[8];
        #pragma unroll
        for (int k = 0; k < 8; k++)
            u[k] = __ldcs(base + ibase + k * 32 + lane);

        unsigned any = 0;
        #pragma unroll
        for (int k = 0; k < 8; k++)
            any |= (u[k].x | u[k].y | u[k].z | u[k].w);

        if (any) {
            int loc[32];
            int cnt = 0;
            #pragma unroll
            for (int k = 0; k < 8; k++) {
                unsigned mk = u[k].x | u[k].y | u[k].z | u[k].w;
                if (mk) {
                    int col0 = (ibase + k * 32 + lane) * 4;
                    if (u[k].x) loc[cnt++] = col0;
                    if (u[k].y) loc[cnt++] = col0 + 1;
                    if (u[k].z) loc[cnt++] = col0 + 2;
                    if (u[k].w) loc[cnt++] = col0 + 3;
                }
            }
            int pos = atomicAdd(&snnz[wlocal], cnt);
            if (pos + cnt <= MAXN) {
                for (int i = 0; i < cnt; i++) {
                    ids[wlocal][pos + i] = loc[i];
                    rowidx[pos + i]      = loc[i];
                }
            }
        }
    }
    __syncwarp();
    int nnz = snnz[wlocal];
    if (lane == 0) g_nnz[row] = nnz;

    // phase 2: gather x over id list -> pooled[row,:]
    int half = lane >> 4;
    int cg   = lane & 15;
    float4 acc = make_float4(0.f, 0.f, 0.f, 0.f);

    int k = half;
    for (; k + 2 < nnz; k += 4) {
        int i0 = ids[wlocal][k];
        int i1 = ids[wlocal][k + 2];
        float4 v0 = *reinterpret_cast<const float4*>(x + (size_t)i0 * HDIM + cg * 4);
        float4 v1 = *reinterpret_cast<const float4*>(x + (size_t)i1 * HDIM + cg * 4);
        acc.x += v0.x + v1.x; acc.y += v0.y + v1.y;
        acc.z += v0.z + v1.z; acc.w += v0.w + v1.w;
    }
    if (k < nnz) {
        int i0 = ids[wlocal][k];
        float4 v0 = *reinterpret_cast<const float4*>(x + (size_t)i0 * HDIM + cg * 4);
        acc.x += v0.x; acc.y += v0.y; acc.z += v0.z; acc.w += v0.w;
    }
    acc.x += __shfl_down_sync(0xffffffffu, acc.x, 16);
    acc.y += __shfl_down_sync(0xffffffffu, acc.y, 16);
    acc.z += __shfl_down_sync(0xffffffffu, acc.z, 16);
    acc.w += __shfl_down_sync(0xffffffffu, acc.w, 16);
    if (half == 0) {
        float inv = 1.0f / (float)nnz;
        float4 r = make_float4(acc.x * inv, acc.y * inv, acc.z * inv, acc.w * inv);
        *reinterpret_cast<float4*>(pooled + (size_t)row * HDIM + cg * 4) = r;
    }
}

// ---------------- K2: sparse mean aggregation, float4 gather, MLP=4 ----------------
// APPLY=1 fuses relu(a*x+b) (g_ab, from bn_finalize) into the gather.
template <int APPLY>
__global__ __launch_bounds__(256) void agg(const float* __restrict__ src,
                                           float* __restrict__ out) {
    int rl  = threadIdx.x >> 6;
    int t6  = threadIdx.x & 63;
    int grp = t6 >> 4;
    int cg  = t6 & 15;
    int r   = ((int)blockIdx.x << 2) + rl;

    __shared__ int    ids[4][MAXN];
    __shared__ float4 red[4][4][16];

    int nnz = g_nnz[r];
    for (int i = t6; i < nnz; i += 64) ids[rl][i] = g_idx[(size_t)r * MAXN + i];
    __syncthreads();

    float4 bna, bnb;
    if (APPLY) {
        bna = *reinterpret_cast<const float4*>(&g_ab[cg * 4]);
        bnb = *reinterpret_cast<const float4*>(&g_ab[64 + cg * 4]);
    }

    float4 acc = make_float4(0.f, 0.f, 0.f, 0.f);
    int k = grp;
    for (; k + 12 < nnz; k += 16) {
        int i0 = ids[rl][k];
        int i1 = ids[rl][k + 4];
        int i2 = ids[rl][k + 8];
        int i3 = ids[rl][k + 12];
        float4 v0 = *reinterpret_cast<const float4*>(src + (size_t)i0 * HDIM + cg * 4);
        float4 v1 = *reinterpret_cast<const float4*>(src + (size_t)i1 * HDIM + cg * 4);
        float4 v2 = *reinterpret_cast<const float4*>(src + (size_t)i2 * HDIM + cg * 4);
        float4 v3 = *reinterpret_cast<const float4*>(src + (size_t)i3 * HDIM + cg * 4);
        if (APPLY) {
            v0.x = fmaxf(fmaf(bna.x, v0.x, bnb.x), 0.f);
            v0.y = fmaxf(fmaf(bna.y, v0.y, bnb.y), 0.f);
            v0.z = fmaxf(fmaf(bna.z, v0.z, bnb.z), 0.f);
            v0.w = fmaxf(fmaf(bna.w, v0.w, bnb.w), 0.f);
            v1.x = fmaxf(fmaf(bna.x, v1.x, bnb.x), 0.f);
            v1.y = fmaxf(fmaf(bna.y, v1.y, bnb.y), 0.f);
            v1.z = fmaxf(fmaf(bna.z, v1.z, bnb.z), 0.f);
            v1.w = fmaxf(fmaf(bna.w, v1.w, bnb.w), 0.f);
            v2.x = fmaxf(fmaf(bna.x, v2.x, bnb.x), 0.f);
            v2.y = fmaxf(fmaf(bna.y, v2.y, bnb.y), 0.f);
            v2.z = fmaxf(fmaf(bna.z, v2.z, bnb.z), 0.f);
            v2.w = fmaxf(fmaf(bna.w, v2.w, bnb.w), 0.f);
            v3.x = fmaxf(fmaf(bna.x, v3.x, bnb.x), 0.f);
            v3.y = fmaxf(fmaf(bna.y, v3.y, bnb.y), 0.f);
            v3.z = fmaxf(fmaf(bna.z, v3.z, bnb.z), 0.f);
            v3.w = fmaxf(fmaf(bna.w, v3.w, bnb.w), 0.f);
        }
        acc.x += (v0.x + v1.x) + (v2.x + v3.x);
        acc.y += (v0.y + v1.y) + (v2.y + v3.y);
        acc.z += (v0.z + v1.z) + (v2.z + v3.z);
        acc.w += (v0.w + v1.w) + (v2.w + v3.w);
    }
    for (; k < nnz; k += 4) {
        int i0 = ids[rl][k];
        float4 v0 = *reinterpret_cast<const float4*>(src + (size_t)i0 * HDIM + cg * 4);
        if (APPLY) {
            v0.x = fmaxf(fmaf(bna.x, v0.x, bnb.x), 0.f);
            v0.y = fmaxf(fmaf(bna.y, v0.y, bnb.y), 0.f);
            v0.z = fmaxf(fmaf(bna.z, v0.z, bnb.z), 0.f);
            v0.w = fmaxf(fmaf(bna.w, v0.w, bnb.w), 0.f);
        }
        acc.x += v0.x; acc.y += v0.y; acc.z += v0.z; acc.w += v0.w;
    }

    red[rl][grp][cg] = acc;
    __syncthreads();

    int col = t6;
    const float* r0 = reinterpret_cast<const float*>(&red[rl][0][col >> 2]);
    const float* r1 = reinterpret_cast<const float*>(&red[rl][1][col >> 2]);
    const float* r2 = reinterpret_cast<const float*>(&red[rl][2][col >> 2]);
    const float* r3 = reinterpret_cast<const float*>(&red[rl][3][col >> 2]);
    int comp = col & 3;
    float s = (r0[comp] + r1[comp]) + (r2[comp] + r3[comp]);
    out[(size_t)r * HDIM + col] = s / (float)g_nnz[r];
}

// ---------------- K3: register-blocked GEMM [16384,64]@[64,64] + bias + BN stats
// 64-row tiles, 4x4 register block per thread (R8 version, measured 8.9us).
// MODE==1 applies relu(a*x+b) (g_ab from bn_finalize) to the input tile.
template <int MODE>
__global__ __launch_bounds__(256) void gemm64(const float* __restrict__ in,
                                              const float* __restrict__ W,
                                              const float* __restrict__ bias,
                                              float* __restrict__ out,
                                              float* __restrict__ part) {
    __shared__ __align__(16) float Ws[64 * 64];      // [k][n]
    __shared__ __align__(16) float Is[64][72];       // 72: 16B-aligned row pad
    __shared__ float redm[16][64];

    int tid = threadIdx.x;
    const float4* W4 = reinterpret_cast<const float4*>(W);
    float4* Ws4 = reinterpret_cast<float4*>(Ws);
    #pragma unroll
    for (int i = tid; i < 1024; i += 256) Ws4[i] = W4[i];

    int row0 = (int)blockIdx.x * 64;
    const float4* in4 = reinterpret_cast<const float4*>(in + (size_t)row0 * HDIM);
    #pragma unroll
    for (int i = tid; i < 1024; i += 256) {
        int rr = i >> 4, cg = i & 15;
        float4 v = in4[i];
        if (MODE == 1) {
            float4 a4 = *reinterpret_cast<const float4*>(&g_ab[cg * 4]);
            float4 b4 = *reinterpret_cast<const float4*>(&g_ab[64 + cg * 4]);
            v.x = fmaxf(fmaf(a4.x, v.x, b4.x), 0.f);
            v.y = fmaxf(fmaf(a4.y, v.y, b4.y), 0.f);
            v.z = fmaxf(fmaf(a4.z, v.z, b4.z), 0.f);
            v.w = fmaxf(fmaf(a4.w, v.w, b4.w), 0.f);
        }
        *reinterpret_cast<float4*>(&Is[rr][cg * 4]) = v;
    }
    __syncthreads();

    int ty = tid >> 4;              // row group: rows ty*4..ty*4+3
    int tx = tid & 15;              // col group: cols tx*4..tx*4+3

    float acc[4][4];
    float4 bv = *reinterpret_cast<const float4*>(bias + tx * 4);
    #pragma unroll
    for (int r = 0; r < 4; r++) {
        acc[r][0] = bv.x; acc[r][1] = bv.y; acc[r][2] = bv.z; acc[r][3] = bv.w;
    }

    #pragma unroll
    for (int k = 0; k < 64; k += 4) {
        float4 w0 = *reinterpret_cast<const float4*>(&Ws[(k + 0) * 64 + tx * 4]);
        float4 w1 = *reinterpret_cast<const float4*>(&Ws[(k + 1) * 64 + tx * 4]);
        float4 w2 = *reinterpret_cast<const float4*>(&Ws[(k + 2) * 64 + tx * 4]);
        float4 w3 = *reinterpret_cast<const float4*>(&Ws[(k + 3) * 64 + tx * 4]);
        #pragma unroll
        for (int r = 0; r < 4; r++) {
            float4 iv = *reinterpret_cast<const float4*>(&Is[ty * 4 + r][k]);
            acc[r][0] = fmaf(iv.x, w0.x, acc[r][0]);
            acc[r][1] = fmaf(iv.x, w0.y, acc[r][1]);
            acc[r][2] = fmaf(iv.x, w0.z, acc[r][2]);
            acc[r][3] = fmaf(iv.x, w0.w, acc[r][3]);
            acc[r][0] = fmaf(iv.y, w1.x, acc[r][0]);
            acc[r][1] = fmaf(iv.y, w1.y, acc[r][1]);
            acc[r][2] = fmaf(iv.y, w1.z, acc[r][2]);
            acc[r][3] = fmaf(iv.y, w1.w, acc[r][3]);
            acc[r][0] = fmaf(iv.z, w2.x, acc[r][0]);
            acc[r][1] = fmaf(iv.z, w2.y, acc[r][1]);
            acc[r][2] = fmaf(iv.z, w2.z, acc[r][2]);
            acc[r][3] = fmaf(iv.z, w2.w, acc[r][3]);
            acc[r][0] = fmaf(iv.w, w3.x, acc[r][0]);
            acc[r][1] = fmaf(iv.w, w3.y, acc[r][1]);
            acc[r][2] = fmaf(iv.w, w3.z, acc[r][2]);
            acc[r][3] = fmaf(iv.w, w3.w, acc[r][3]);
        }
    }

    #pragma unroll
    for (int r = 0; r < 4; r++) {
        float4 o = make_float4(acc[r][0], acc[r][1], acc[r][2], acc[r][3]);
        *reinterpret_cast<float4*>(out + (size_t)(row0 + ty * 4 + r) * HDIM + tx * 4) = o;
    }

    // per-block column stats: sum then sumsq
    float s[4];
    #pragma unroll
    for (int j = 0; j < 4; j++)
        s[j] = (acc[0][j] + acc[1][j]) + (acc[2][j] + acc[3][j]);
    #pragma unroll
    for (int j = 0; j < 4; j++) redm[ty][tx * 4 + j] = s[j];
    __syncthreads();
    if (tid < 64) {
        float v = 0.f;
        #pragma unroll
        for (int i = 0; i < 16; i++) v += redm[i][tid];
        part[(size_t)blockIdx.x * 128 + tid] = v;
    }
    __syncthreads();
    #pragma unroll
    for (int j = 0; j < 4; j++) {
        float q = (acc[0][j] * acc[0][j] + acc[1][j] * acc[1][j]) +
                  (acc[2][j] * acc[2][j] + acc[3][j] * acc[3][j]);
        redm[ty][tx * 4 + j] = q;
    }
    __syncthreads();
    if (tid < 64) {
        float v = 0.f;
        #pragma unroll
        for (int i = 0; i < 16; i++) v += redm[i][tid];
        part[(size_t)blockIdx.x * 128 + 64 + tid] = v;
    }
}

// ---------------- K4: reduce partials -> BN affine coefficients ----------------
__global__ __launch_bounds__(256) void bn_finalize(const float* __restrict__ g,
                                                   const float* __restrict__ be) {
    int c = blockIdx.x;                      // column 0..63
    int t = threadIdx.x;

    float s = 0.f, q = 0.f;
    #pragma unroll
    for (int b = t; b < NBLK; b += 256) {
        s += g_part[(size_t)b * 128 + c];
        q += g_part[(size_t)b * 128 + 64 + c];
    }
    __shared__ float ss[256];
    __shared__ float qq[256];
    ss[t] = s; qq[t] = q;
    __syncthreads();
    #pragma unroll
    for (int o = 128; o > 0; o >>= 1) {
        if (t < o) { ss[t] += ss[t + o]; qq[t] += qq[t + o]; }
        __syncthreads();
    }
    if (t == 0) {
        const float invn = 1.0f / (float)N_NODES;
        float mean = ss[0] * invn;
        float var  = qq[0] * invn - mean * mean;
        float a = g[c] * rsqrtf(var + BN_EPS);
        g_ab[c]      = a;
        g_ab[64 + c] = be[c] - mean * a;
    }
}

// ---------------- K5: elementwise h = relu(a*t2 + b) (final layer only) ----------------
__global__ __launch_bounds__(256) void apply_bn_relu(const float* __restrict__ t2,
                                                     float* __restrict__ h) {
    int i = blockIdx.x * 256 + threadIdx.x;
    int c = i & 63;
    h[i] = fmaxf(fmaf(g_ab[c], t2[i], g_ab[64 + c]), 0.f);
}

// ---------------- K6: pooled_h = graph_pool @ h  (general dense, zero-skip) ----------------
__global__ __launch_bounds__(256) void pool(const float* __restrict__ gp,
                                            const float* __restrict__ h,
                                            float* __restrict__ out) {
    int g = blockIdx.x;                 // 128 graphs
    int c    = threadIdx.x & 63;
    int lane = threadIdx.x >> 6;        // 4 node-lanes (warp-uniform)
    const float* gprow = gp + (size_t)g * N_NODES;

    float acc = 0.f;
    for (int n0 = lane; n0 < N_NODES; n0 += 32) {
        #pragma unroll
        for (int u = 0; u < 8; u++) {
            int n = n0 + u * 4;
            float w = __ldcs(gprow + n);
            if (w != 0.f) acc = fmaf(w, h[(size_t)n * HDIM + c], acc);
        }
    }
    __shared__ float red[4][64];
    red[lane][c] = acc;
    __syncthreads();
    if (threadIdx.x < 64)
        out[(size_t)g * HDIM + threadIdx.x] =
            (red[0][threadIdx.x] + red[1][threadIdx.x]) +
            (red[2][threadIdx.x] + red[3][threadIdx.x]);
}

// ---------------- launch ----------------
extern "C" void kernel_launch(void* const* d_in, const int* in_sizes, int n_in,
                              void* d_out, int out_size) {
    const float* x   = (const float*)d_in[0];
    const float* adj = (const float*)d_in[1];
    const float* gp  = (const float*)d_in[2];

    const float* P[16];
    for (int i = 0; i < 16; i++) P[i] = (const float*)d_in[3 + i];

    float* out      = (float*)d_out;
    float* h_nodes  = out + 128 * HDIM;   // [16384,64] after the [128,64] readout

    float *pooled, *t, *t2, *part;
    cudaGetSymbolAddress((void**)&pooled, g_pooled);
    cudaGetSymbolAddress((void**)&t,      g_t);
    cudaGetSymbolAddress((void**)&t2,     g_t2);
    cudaGetSymbolAddress((void**)&part,   g_part);

    // 1) fused: adj scan -> CSR + degrees + layer-0 aggregation (single launch)
    scan_agg<<<2048, 256>>>(adj, x, pooled);

    // ---- layer 0 MLP ----
    gemm64<0><<<NBLK, 256>>>(pooled, P[0], P[1], t, part);
    bn_finalize<<<64, 256>>>(P[2], P[3]);               // g1_0, be1_0
    gemm64<1><<<NBLK, 256>>>(t, P[4], P[5], t2, part);
    bn_finalize<<<64, 256>>>(P[6], P[7]);               // g_0, be_0

    // ---- layer 1 (outer BN+ReLU of layer 0 fused into the gather) ----
    agg<1><<<N_NODES / 4, 256>>>(t2, pooled);
    gemm64<0><<<NBLK, 256>>>(pooled, P[8], P[9], t, part);
    bn_finalize<<<64, 256>>>(P[10], P[11]);             // g1_1, be1_1
    gemm64<1><<<NBLK, 256>>>(t, P[12], P[13], t2, part);
    bn_finalize<<<64, 256>>>(P[14], P[15]);             // g_1, be_1
    apply_bn_relu<<<(N_NODES * HDIM) / 256, 256>>>(t2, h_nodes);

    // ---- graph readout ----
    pool<<<128, 256>>>(gp, h_nodes, out);

    (void)in_sizes; (void)n_in; (void)out_size;
}